// round 4
// baseline (speedup 1.0000x reference)
#include <cuda_runtime.h>
#include <cuda_bf16.h>
#include <math.h>

// Problem constants
#define B_   16
#define L_   128
#define KW   8
#define NPAIR 2104
#define GCN  512
#define PE   64
#define PF   1088
#define PFP  1152
#define M_   2048
#define NREL 17
#define NT   48           // k-tiles: 3 segments x 16 tiles of 32

// ---------------- scratch ----------------------------------------------------
__device__ float g_Aemo[M_ * PF];
__device__ float g_Acau[M_ * PF];
__device__ float g_Apos[NREL * PF];
__device__ float g_f[NREL * PE];
__device__ int   g_poff[L_];            // pair offset per i
__device__ __nv_bfloat16 g_Ahi[2][M_ * GCN];
__device__ __nv_bfloat16 g_Alo[2][M_ * GCN];
__device__ __nv_bfloat16 g_Bhi[2][PFP * GCN];
__device__ __nv_bfloat16 g_Blo[2][PFP * GCN];

// ---------------- init: pair offsets + emo_cau_pos tail ----------------------
__global__ void init_pairs_kernel(float* __restrict__ out, int out_size) {
    int i = threadIdx.x;
    if (i >= L_) return;
    int off = 0;
    for (int t = 0; t < i; t++) {
        int lo = t - KW; if (lo < 0) lo = 0;
        int hi = t + KW; if (hi > L_ - 1) hi = L_ - 1;
        off += hi - lo + 1;
    }
    g_poff[i] = off;
    int lo = i - KW; if (lo < 0) lo = 0;
    int hi = i + KW; if (hi > L_ - 1) hi = L_ - 1;
    bool write_pos = (out_size == B_ * NPAIR + 2 * NPAIR);
    if (write_pos) {
        for (int j = lo; j <= hi; j++) {
            int p = off + (j - lo);
            out[B_ * NPAIR + 2 * p + 0] = (float)(i + 1);
            out[B_ * NPAIR + 2 * p + 1] = (float)(j + 1);
        }
    }
}

// ---------------- init: smoothed positional table f [17 x 64] ----------------
__global__ void init_f_kernel(const float* __restrict__ pos_emb) {
    int idx = blockIdx.x * blockDim.x + threadIdx.x;
    if (idx >= NREL * PE) return;
    int r = idx / PE;
    int e = idx % PE;
    float s = 0.f;
    #pragma unroll
    for (int d = 0; d < NREL; d++) {
        int ad = d - KW; if (ad < 0) ad = -ad;
        float cnt = (float)(L_ - ad);
        int dd = r - d;
        float w = cnt * expf(-(float)(dd * dd));
        s += w * pos_emb[d * PE + e];
    }
    g_f[idx] = s;
}

// ---------------- init: A_pos (includes b1) ----------------------------------
__global__ void init_apos_kernel(const float* __restrict__ W1,
                                 const float* __restrict__ b1) {
    int idx = blockIdx.x * blockDim.x + threadIdx.x;
    if (idx >= NREL * PF) return;
    int r = idx / PF;
    int g = idx % PF;
    float s = b1[g];
    const float* w = W1 + g * PF + 2 * GCN;
    const float* f = g_f + r * PE;
    #pragma unroll 8
    for (int e = 0; e < PE; e++) s += f[e] * w[e];
    g_Apos[idx] = s;
}

// ---------------- convert: X -> hi/lo bf16 (vectorized) ----------------------
__global__ void conv_x_kernel(const float* __restrict__ Xe,
                              const float* __restrict__ Xc) {
    int idx = blockIdx.x * blockDim.x + threadIdx.x;     // float4 index
    if (idx >= M_ * GCN / 4) return;
    #pragma unroll
    for (int z = 0; z < 2; z++) {
        const float* X = z ? Xc : Xe;
        float4 v = *(const float4*)(X + idx * 4);
        __nv_bfloat16 h0 = __float2bfloat16(v.x);
        __nv_bfloat16 h1 = __float2bfloat16(v.y);
        __nv_bfloat16 h2 = __float2bfloat16(v.z);
        __nv_bfloat16 h3 = __float2bfloat16(v.w);
        __nv_bfloat162* hp = (__nv_bfloat162*)(&g_Ahi[z][idx * 4]);
        hp[0] = __nv_bfloat162(h0, h1);
        hp[1] = __nv_bfloat162(h2, h3);
        __nv_bfloat162* lp = (__nv_bfloat162*)(&g_Alo[z][idx * 4]);
        lp[0] = __nv_bfloat162(__float2bfloat16(v.x - __bfloat162float(h0)),
                               __float2bfloat16(v.y - __bfloat162float(h1)));
        lp[1] = __nv_bfloat162(__float2bfloat16(v.z - __bfloat162float(h2)),
                               __float2bfloat16(v.w - __bfloat162float(h3)));
    }
}

// ---------------- convert: W1 -> hi/lo bf16 (vectorized) ---------------------
__global__ void conv_w_kernel(const float* __restrict__ W1) {
    int idx = blockIdx.x * blockDim.x + threadIdx.x;     // float4 index over PF*GCN
    if (idx >= PF * GCN / 4) return;
    int g = idx / (GCN / 4), kq = idx % (GCN / 4);
    #pragma unroll
    for (int z = 0; z < 2; z++) {
        float4 v = *(const float4*)(W1 + (size_t)g * PF + z * GCN + kq * 4);
        __nv_bfloat16 h0 = __float2bfloat16(v.x);
        __nv_bfloat16 h1 = __float2bfloat16(v.y);
        __nv_bfloat16 h2 = __float2bfloat16(v.z);
        __nv_bfloat16 h3 = __float2bfloat16(v.w);
        __nv_bfloat162* hp = (__nv_bfloat162*)(&g_Bhi[z][(size_t)g * GCN + kq * 4]);
        hp[0] = __nv_bfloat162(h0, h1);
        hp[1] = __nv_bfloat162(h2, h3);
        __nv_bfloat162* lp = (__nv_bfloat162*)(&g_Blo[z][(size_t)g * GCN + kq * 4]);
        lp[0] = __nv_bfloat162(__float2bfloat16(v.x - __bfloat162float(h0)),
                               __float2bfloat16(v.y - __bfloat162float(h1)));
        lp[1] = __nv_bfloat162(__float2bfloat16(v.z - __bfloat162float(h2)),
                               __float2bfloat16(v.w - __bfloat162float(h3)));
    }
}

// ---------------- bf16 tensor-core GEMM (128x128x32, ldmatrix, 4-stage) ------
#define BM 128
#define BN 128
#define BK 32
#define SSTR 40
#define NSTAGE 4
#define SA_ELEMS (BM * SSTR)
#define SB_ELEMS (BN * SSTR)
#define STAGE_ELEMS (SA_ELEMS + SB_ELEMS)

__device__ __forceinline__ void cp16(void* smem, const void* g) {
    unsigned s = (unsigned)__cvta_generic_to_shared(smem);
    asm volatile("cp.async.cg.shared.global [%0], [%1], 16;\n" :: "r"(s), "l"(g));
}
#define CP_COMMIT() asm volatile("cp.async.commit_group;\n" ::: "memory")
#define CP_WAIT2()  asm volatile("cp.async.wait_group 2;\n" ::: "memory")

__device__ __forceinline__ void ldsm4(unsigned& r0, unsigned& r1,
                                      unsigned& r2, unsigned& r3,
                                      const __nv_bfloat16* p) {
    unsigned a = (unsigned)__cvta_generic_to_shared(p);
    asm volatile("ldmatrix.sync.aligned.m8n8.x4.shared.b16 {%0,%1,%2,%3}, [%4];\n"
                 : "=r"(r0), "=r"(r1), "=r"(r2), "=r"(r3) : "r"(a));
}

extern __shared__ __align__(16) unsigned char dynraw[];

__global__ void __launch_bounds__(256, 2)
mma_gemm_kernel() {
    __nv_bfloat16* dynsmem = (__nv_bfloat16*)dynraw;
    const int z = blockIdx.z;
    const __nv_bfloat16* __restrict__ Ahi = g_Ahi[z];
    const __nv_bfloat16* __restrict__ Alo = g_Alo[z];
    const __nv_bfloat16* __restrict__ Bhi = g_Bhi[z];
    const __nv_bfloat16* __restrict__ Blo = g_Blo[z];
    float* __restrict__ C = z ? g_Acau : g_Aemo;

    const int tid  = threadIdx.x;
    const int lane = tid & 31;
    const int wid  = tid >> 5;
    const int wmBase = (wid & 1) * 64;
    const int wnBase = (wid >> 1) * 32;
    const int m0 = blockIdx.y * BM;
    const int n0 = blockIdx.x * BN;

    const int aRow = (lane & 7) + ((lane >> 3) & 1) * 8;
    const int aK   = (lane >> 4) * 8;
    const int bRow = (lane & 7) + (lane >> 4) * 8;
    const int bK   = ((lane >> 3) & 1) * 8;

    float acc[4][4][4];
    #pragma unroll
    for (int mt = 0; mt < 4; mt++)
        #pragma unroll
        for (int nt = 0; nt < 4; nt++)
            #pragma unroll
            for (int e = 0; e < 4; e++) acc[mt][nt][e] = 0.f;

    auto load_stage = [&](int kt, int s) {
        const int seg = kt >> 4;
        const int kc  = (kt & 15) * BK;
        const __nv_bfloat16* __restrict__ Asrc = (seg < 2) ? Ahi : Alo;
        const __nv_bfloat16* __restrict__ Bsrc = (seg == 1) ? Blo : Bhi;
        __nv_bfloat16* sA = dynsmem + s * STAGE_ELEMS;
        __nv_bfloat16* sB = sA + SA_ELEMS;
        #pragma unroll
        for (int l = 0; l < 2; l++) {
            int q = tid + l * 256;
            int row = q >> 2, c8 = (q & 3) * 8;
            cp16(&sA[row * SSTR + c8],
                 Asrc + (size_t)(m0 + row) * GCN + kc + c8);
        }
        #pragma unroll
        for (int l = 0; l < 2; l++) {
            int q = tid + l * 256;
            int row = q >> 2, c8 = (q & 3) * 8;
            cp16(&sB[row * SSTR + c8],
                 Bsrc + (size_t)(n0 + row) * GCN + kc + c8);
        }
    };

    load_stage(0, 0); CP_COMMIT();
    load_stage(1, 1); CP_COMMIT();
    load_stage(2, 2); CP_COMMIT();

    for (int kt = 0; kt < NT; kt++) {
        CP_WAIT2();
        __syncthreads();
        if (kt + 3 < NT) load_stage(kt + 3, (kt + 3) % NSTAGE);
        CP_COMMIT();

        const int s = kt % NSTAGE;
        const __nv_bfloat16* sA = dynsmem + s * STAGE_ELEMS;
        const __nv_bfloat16* sB = sA + SA_ELEMS;

        #pragma unroll
        for (int kk = 0; kk < BK; kk += 16) {
            unsigned a[4][4], b[2][4];
            #pragma unroll
            for (int mt = 0; mt < 4; mt++)
                ldsm4(a[mt][0], a[mt][1], a[mt][2], a[mt][3],
                      &sA[(wmBase + mt * 16 + aRow) * SSTR + kk + aK]);
            #pragma unroll
            for (int ntp = 0; ntp < 2; ntp++)
                ldsm4(b[ntp][0], b[ntp][1], b[ntp][2], b[ntp][3],
                      &sB[(wnBase + ntp * 16 + bRow) * SSTR + kk + bK]);
            #pragma unroll
            for (int mt = 0; mt < 4; mt++)
                #pragma unroll
                for (int nt = 0; nt < 4; nt++) {
                    unsigned b0 = b[nt >> 1][(nt & 1) * 2];
                    unsigned b1 = b[nt >> 1][(nt & 1) * 2 + 1];
                    asm volatile(
                        "mma.sync.aligned.m16n8k16.row.col.f32.bf16.bf16.f32 "
                        "{%0,%1,%2,%3}, {%4,%5,%6,%7}, {%8,%9}, {%0,%1,%2,%3};\n"
                        : "+f"(acc[mt][nt][0]), "+f"(acc[mt][nt][1]),
                          "+f"(acc[mt][nt][2]), "+f"(acc[mt][nt][3])
                        : "r"(a[mt][0]), "r"(a[mt][1]), "r"(a[mt][2]), "r"(a[mt][3]),
                          "r"(b0), "r"(b1));
                }
        }
    }

    #pragma unroll
    for (int mt = 0; mt < 4; mt++) {
        int row = m0 + wmBase + mt * 16 + (lane >> 2);
        #pragma unroll
        for (int nt = 0; nt < 4; nt++) {
            int col = n0 + wnBase + nt * 8 + (lane & 3) * 2;
            if (col < PF) {
                *(float2*)&C[(size_t)row * PF + col] =
                    make_float2(acc[mt][nt][0], acc[mt][nt][1]);
                *(float2*)&C[(size_t)(row + 8) * PF + col] =
                    make_float2(acc[mt][nt][2], acc[mt][nt][3]);
            }
        }
    }
}

// ---------------- tiled epilogue ---------------------------------------------
// CTA = (i-chunk of EI, batch b). Stage EI emo rows + cau window + W2 in smem.
#define EI 4
#define MAXC (EI + 2 * KW)    // 20 cau rows max

__global__ void __launch_bounds__(256)
epilogue_kernel(const float* __restrict__ W2, const float* __restrict__ b2,
                float* __restrict__ out) {
    float* sE = (float*)dynraw;               // [EI * PF]
    float* sC = sE + EI * PF;                 // [MAXC * PF]
    float* sW = sC + MAXC * PF;               // [PF]
    __shared__ int sPi[EI * NREL], sPj[EI * NREL], sPp[EI * NREL];
    __shared__ int sCnt;

    const int tid = threadIdx.x;
    const int lane = tid & 31;
    const int wid = tid >> 5;
    const int i0 = blockIdx.x * EI;
    const int b  = blockIdx.y;

    int j0 = i0 - KW; if (j0 < 0) j0 = 0;
    int j1 = i0 + EI - 1 + KW; if (j1 > L_ - 1) j1 = L_ - 1;
    const int nc = j1 - j0 + 1;

    // build pair list (single thread; cheap)
    if (tid == 0) {
        int c = 0;
        for (int ii = i0; ii < i0 + EI; ii++) {
            int lo = ii - KW; if (lo < 0) lo = 0;
            int hi = ii + KW; if (hi > L_ - 1) hi = L_ - 1;
            int off = g_poff[ii];
            for (int jj = lo; jj <= hi; jj++) {
                sPi[c] = ii - i0;
                sPj[c] = jj - j0;
                sPp[c] = off + (jj - lo);
                c++;
            }
        }
        sCnt = c;
    }

    // stage rows into smem (float4 coalesced)
    {
        const float4* src = (const float4*)(g_Aemo + (size_t)(b * L_ + i0) * PF);
        float4* dst = (float4*)sE;
        for (int q = tid; q < EI * PF / 4; q += 256) dst[q] = src[q];
    }
    {
        const float4* src = (const float4*)(g_Acau + (size_t)(b * L_ + j0) * PF);
        float4* dst = (float4*)sC;
        for (int q = tid; q < nc * PF / 4; q += 256) dst[q] = src[q];
    }
    {
        const float4* src = (const float4*)W2;
        float4* dst = (float4*)sW;
        for (int q = tid; q < PF / 4; q += 256) dst[q] = src[q];
    }
    __syncthreads();

    const float bias = b2[0];
    const int cnt = sCnt;

    for (int pc = wid; pc < cnt; pc += 8) {
        const float4* ae = (const float4*)(sE + (size_t)sPi[pc] * PF);
        const float4* ac = (const float4*)(sC + (size_t)sPj[pc] * PF);
        int r = (sPj[pc] + j0) - (sPi[pc] + i0) + KW;
        const float4* ap = (const float4*)(g_Apos + (size_t)r * PF);
        const float4* w2 = (const float4*)sW;

        float sum = 0.f;
        #pragma unroll
        for (int t = 0; t < 9; t++) {
            int c4 = t * 32 + lane;
            if (c4 < PF / 4) {
                float4 e = ae[c4];
                float4 c = ac[c4];
                float4 q = __ldg(&ap[c4]);
                float4 w = w2[c4];
                float v0 = fmaxf(e.x + c.x + q.x, 0.f);
                float v1 = fmaxf(e.y + c.y + q.y, 0.f);
                float v2 = fmaxf(e.z + c.z + q.z, 0.f);
                float v3 = fmaxf(e.w + c.w + q.w, 0.f);
                sum = fmaf(v0, w.x, sum);
                sum = fmaf(v1, w.y, sum);
                sum = fmaf(v2, w.z, sum);
                sum = fmaf(v3, w.w, sum);
            }
        }
        #pragma unroll
        for (int o = 16; o > 0; o >>= 1)
            sum += __shfl_xor_sync(0xFFFFFFFF, sum, o);
        if (lane == 0) out[b * NPAIR + sPp[pc]] = sum + bias;
    }
}

// ---------------- launch ------------------------------------------------------
extern "C" void kernel_launch(void* const* d_in, const int* in_sizes, int n_in,
                              void* d_out, int out_size) {
    const float* h_emo  = (const float*)d_in[0];
    const float* h_cau  = (const float*)d_in[1];
    const float* pos    = (const float*)d_in[2];
    const float* W1     = (const float*)d_in[3];
    const float* b1     = (const float*)d_in[4];
    const float* W2     = (const float*)d_in[5];
    const float* b2     = (const float*)d_in[6];
    float* out = (float*)d_out;

    const int gemm_smem = NSTAGE * STAGE_ELEMS * (int)sizeof(__nv_bfloat16);
    const int epi_smem  = (EI * PF + MAXC * PF + PF) * (int)sizeof(float);
    static bool configured = false;
    if (!configured) {
        cudaFuncSetAttribute(mma_gemm_kernel,
                             cudaFuncAttributeMaxDynamicSharedMemorySize, gemm_smem);
        cudaFuncSetAttribute(epilogue_kernel,
                             cudaFuncAttributeMaxDynamicSharedMemorySize, epi_smem);
        configured = true;
    }

    init_pairs_kernel<<<1, 128>>>(out, out_size);
    init_f_kernel<<<(NREL * PE + 255) / 256, 256>>>(pos);
    init_apos_kernel<<<(NREL * PF + 255) / 256, 256>>>(W1, b1);
    conv_x_kernel<<<(M_ * GCN / 4 + 255) / 256, 256>>>(h_emo, h_cau);
    conv_w_kernel<<<(PF * GCN / 4 + 255) / 256, 256>>>(W1);

    dim3 ggrid(PFP / BN, M_ / BM, 2);   // (9, 16, 2)
    mma_gemm_kernel<<<ggrid, 256, gemm_smem>>>();

    dim3 egrid(L_ / EI, B_);            // (32, 16)
    epilogue_kernel<<<egrid, 256, epi_smem>>>(W2, b2, out);
}

// round 6
// speedup vs baseline: 1.0201x; 1.0201x over previous
#include <cuda_runtime.h>
#include <cuda_bf16.h>
#include <math.h>
#include <stdint.h>

// Problem constants
#define B_   16
#define L_   128
#define KW   8
#define NPAIR 2104
#define GCN  512
#define PE   64
#define PF   1088
#define PFP  1152
#define M_   2048
#define NREL 17
#define NT   48           // k-tiles: 3 segments x 16 tiles of 32

// ---------------- scratch ----------------------------------------------------
__device__ float g_Aemo[M_ * PF];
__device__ float g_Acau[M_ * PF];
__device__ float g_Apos[NREL * PF];
__device__ float g_f[NREL * PE];
__device__ int   g_poff[L_];
__device__ __nv_bfloat16 g_Ahi[2][M_ * GCN];
__device__ __nv_bfloat16 g_Alo[2][M_ * GCN];
__device__ __nv_bfloat16 g_Bhi[2][PFP * GCN];
__device__ __nv_bfloat16 g_Blo[2][PFP * GCN];

// ---------------- init: pair offsets + emo_cau_pos tail ----------------------
__global__ void init_pairs_kernel(float* __restrict__ out, int out_size) {
    int i = threadIdx.x;
    if (i >= L_) return;
    int off = 0;
    for (int t = 0; t < i; t++) {
        int lo = t - KW; if (lo < 0) lo = 0;
        int hi = t + KW; if (hi > L_ - 1) hi = L_ - 1;
        off += hi - lo + 1;
    }
    g_poff[i] = off;
    int lo = i - KW; if (lo < 0) lo = 0;
    int hi = i + KW; if (hi > L_ - 1) hi = L_ - 1;
    if (out_size == B_ * NPAIR + 2 * NPAIR) {
        for (int j = lo; j <= hi; j++) {
            int p = off + (j - lo);
            out[B_ * NPAIR + 2 * p + 0] = (float)(i + 1);
            out[B_ * NPAIR + 2 * p + 1] = (float)(j + 1);
        }
    }
}

// ---------------- init: smoothed positional table f [17 x 64] ----------------
__global__ void init_f_kernel(const float* __restrict__ pos_emb) {
    int idx = blockIdx.x * blockDim.x + threadIdx.x;
    if (idx >= NREL * PE) return;
    int r = idx / PE;
    int e = idx % PE;
    float s = 0.f;
    #pragma unroll
    for (int d = 0; d < NREL; d++) {
        int ad = d - KW; if (ad < 0) ad = -ad;
        float cnt = (float)(L_ - ad);
        int dd = r - d;
        float w = cnt * expf(-(float)(dd * dd));
        s += w * pos_emb[d * PE + e];
    }
    g_f[idx] = s;
}

// ---------------- init: A_pos (includes b1) ----------------------------------
__global__ void init_apos_kernel(const float* __restrict__ W1,
                                 const float* __restrict__ b1) {
    int idx = blockIdx.x * blockDim.x + threadIdx.x;
    if (idx >= NREL * PF) return;
    int r = idx / PF;
    int g = idx % PF;
    float s = b1[g];
    const float* w = W1 + g * PF + 2 * GCN;
    const float* f = g_f + r * PE;
    #pragma unroll 8
    for (int e = 0; e < PE; e++) s += f[e] * w[e];
    g_Apos[idx] = s;
}

// ---------------- convert: X -> hi/lo bf16 (vectorized) ----------------------
__global__ void conv_x_kernel(const float* __restrict__ Xe,
                              const float* __restrict__ Xc) {
    int idx = blockIdx.x * blockDim.x + threadIdx.x;
    if (idx >= M_ * GCN / 4) return;
    #pragma unroll
    for (int z = 0; z < 2; z++) {
        const float* X = z ? Xc : Xe;
        float4 v = *(const float4*)(X + (size_t)idx * 4);
        __nv_bfloat16 h0 = __float2bfloat16(v.x);
        __nv_bfloat16 h1 = __float2bfloat16(v.y);
        __nv_bfloat16 h2 = __float2bfloat16(v.z);
        __nv_bfloat16 h3 = __float2bfloat16(v.w);
        __nv_bfloat162* hp = (__nv_bfloat162*)(&g_Ahi[z][(size_t)idx * 4]);
        hp[0] = __nv_bfloat162(h0, h1);
        hp[1] = __nv_bfloat162(h2, h3);
        __nv_bfloat162* lp = (__nv_bfloat162*)(&g_Alo[z][(size_t)idx * 4]);
        lp[0] = __nv_bfloat162(__float2bfloat16(v.x - __bfloat162float(h0)),
                               __float2bfloat16(v.y - __bfloat162float(h1)));
        lp[1] = __nv_bfloat162(__float2bfloat16(v.z - __bfloat162float(h2)),
                               __float2bfloat16(v.w - __bfloat162float(h3)));
    }
}

// ---------------- convert: W1 -> hi/lo bf16 (vectorized) ---------------------
__global__ void conv_w_kernel(const float* __restrict__ W1) {
    int idx = blockIdx.x * blockDim.x + threadIdx.x;
    if (idx >= PF * GCN / 4) return;
    int g = idx / (GCN / 4), kq = idx % (GCN / 4);
    #pragma unroll
    for (int z = 0; z < 2; z++) {
        float4 v = *(const float4*)(W1 + (size_t)g * PF + z * GCN + kq * 4);
        __nv_bfloat16 h0 = __float2bfloat16(v.x);
        __nv_bfloat16 h1 = __float2bfloat16(v.y);
        __nv_bfloat16 h2 = __float2bfloat16(v.z);
        __nv_bfloat16 h3 = __float2bfloat16(v.w);
        __nv_bfloat162* hp = (__nv_bfloat162*)(&g_Bhi[z][(size_t)g * GCN + kq * 4]);
        hp[0] = __nv_bfloat162(h0, h1);
        hp[1] = __nv_bfloat162(h2, h3);
        __nv_bfloat162* lp = (__nv_bfloat162*)(&g_Blo[z][(size_t)g * GCN + kq * 4]);
        lp[0] = __nv_bfloat162(__float2bfloat16(v.x - __bfloat162float(h0)),
                               __float2bfloat16(v.y - __bfloat162float(h1)));
        lp[1] = __nv_bfloat162(__float2bfloat16(v.z - __bfloat162float(h2)),
                               __float2bfloat16(v.w - __bfloat162float(h3)));
    }
}

// ---------------- bf16 tensor-core GEMM (128x128x32, ldmatrix, 3-stage) ------
#define BM 128
#define BN 128
#define BK 32
#define SSTR 40
#define NSTAGE 3
#define SA_ELEMS (BM * SSTR)
#define SB_ELEMS (BN * SSTR)
#define STAGE_ELEMS (SA_ELEMS + SB_ELEMS)

__device__ __forceinline__ void cp16(void* smem, const void* g) {
    unsigned s = (unsigned)__cvta_generic_to_shared(smem);
    asm volatile("cp.async.cg.shared.global [%0], [%1], 16;\n" :: "r"(s), "l"(g));
}
#define CP_COMMIT() asm volatile("cp.async.commit_group;\n" ::: "memory")
#define CP_WAIT1()  asm volatile("cp.async.wait_group 1;\n" ::: "memory")

__device__ __forceinline__ void ldsm4(unsigned& r0, unsigned& r1,
                                      unsigned& r2, unsigned& r3,
                                      const __nv_bfloat16* p) {
    unsigned a = (unsigned)__cvta_generic_to_shared(p);
    asm volatile("ldmatrix.sync.aligned.m8n8.x4.shared.b16 {%0,%1,%2,%3}, [%4];\n"
                 : "=r"(r0), "=r"(r1), "=r"(r2), "=r"(r3) : "r"(a));
}

extern __shared__ __align__(16) unsigned char dynraw[];

__global__ void __launch_bounds__(256, 2)
mma_gemm_kernel() {
    __nv_bfloat16* dynsmem = (__nv_bfloat16*)dynraw;
    const int z = blockIdx.z;
    const __nv_bfloat16* __restrict__ Ahi = g_Ahi[z];
    const __nv_bfloat16* __restrict__ Alo = g_Alo[z];
    const __nv_bfloat16* __restrict__ Bhi = g_Bhi[z];
    const __nv_bfloat16* __restrict__ Blo = g_Blo[z];
    float* __restrict__ C = z ? g_Acau : g_Aemo;

    const int tid  = threadIdx.x;
    const int lane = tid & 31;
    const int wid  = tid >> 5;
    const int wmBase = (wid & 1) * 64;
    const int wnBase = (wid >> 1) * 32;
    const int m0 = blockIdx.y * BM;
    const int n0 = blockIdx.x * BN;

    const int aRow = (lane & 7) + ((lane >> 3) & 1) * 8;
    const int aK   = (lane >> 4) * 8;
    const int bRow = (lane & 7) + (lane >> 4) * 8;
    const int bK   = ((lane >> 3) & 1) * 8;

    float acc[4][4][4];
    #pragma unroll
    for (int mt = 0; mt < 4; mt++)
        #pragma unroll
        for (int nt = 0; nt < 4; nt++)
            #pragma unroll
            for (int e = 0; e < 4; e++) acc[mt][nt][e] = 0.f;

    auto load_stage = [&](int kt, int s) {
        const int seg = kt >> 4;
        const int kc  = (kt & 15) * BK;
        const __nv_bfloat16* __restrict__ Asrc = (seg < 2) ? Ahi : Alo;
        const __nv_bfloat16* __restrict__ Bsrc = (seg == 1) ? Blo : Bhi;
        __nv_bfloat16* sA = dynsmem + s * STAGE_ELEMS;
        __nv_bfloat16* sB = sA + SA_ELEMS;
        #pragma unroll
        for (int l = 0; l < 2; l++) {
            int q = tid + l * 256;
            int row = q >> 2, c8 = (q & 3) * 8;
            cp16(&sA[row * SSTR + c8],
                 Asrc + (size_t)(m0 + row) * GCN + kc + c8);
        }
        #pragma unroll
        for (int l = 0; l < 2; l++) {
            int q = tid + l * 256;
            int row = q >> 2, c8 = (q & 3) * 8;
            cp16(&sB[row * SSTR + c8],
                 Bsrc + (size_t)(n0 + row) * GCN + kc + c8);
        }
    };

    load_stage(0, 0); CP_COMMIT();
    load_stage(1, 1); CP_COMMIT();

    for (int kt = 0; kt < NT; kt++) {
        CP_WAIT1();
        __syncthreads();
        if (kt + 2 < NT) load_stage(kt + 2, (kt + 2) % NSTAGE);
        CP_COMMIT();

        const int s = kt % NSTAGE;
        const __nv_bfloat16* sA = dynsmem + s * STAGE_ELEMS;
        const __nv_bfloat16* sB = sA + SA_ELEMS;

        #pragma unroll
        for (int kk = 0; kk < BK; kk += 16) {
            unsigned a[4][4], b[2][4];
            #pragma unroll
            for (int mt = 0; mt < 4; mt++)
                ldsm4(a[mt][0], a[mt][1], a[mt][2], a[mt][3],
                      &sA[(wmBase + mt * 16 + aRow) * SSTR + kk + aK]);
            #pragma unroll
            for (int ntp = 0; ntp < 2; ntp++)
                ldsm4(b[ntp][0], b[ntp][1], b[ntp][2], b[ntp][3],
                      &sB[(wnBase + ntp * 16 + bRow) * SSTR + kk + bK]);
            #pragma unroll
            for (int mt = 0; mt < 4; mt++)
                #pragma unroll
                for (int nt = 0; nt < 4; nt++) {
                    unsigned b0 = b[nt >> 1][(nt & 1) * 2];
                    unsigned b1 = b[nt >> 1][(nt & 1) * 2 + 1];
                    asm volatile(
                        "mma.sync.aligned.m16n8k16.row.col.f32.bf16.bf16.f32 "
                        "{%0,%1,%2,%3}, {%4,%5,%6,%7}, {%8,%9}, {%0,%1,%2,%3};\n"
                        : "+f"(acc[mt][nt][0]), "+f"(acc[mt][nt][1]),
                          "+f"(acc[mt][nt][2]), "+f"(acc[mt][nt][3])
                        : "r"(a[mt][0]), "r"(a[mt][1]), "r"(a[mt][2]), "r"(a[mt][3]),
                          "r"(b0), "r"(b1));
                }
        }
    }

    #pragma unroll
    for (int mt = 0; mt < 4; mt++) {
        int row = m0 + wmBase + mt * 16 + (lane >> 2);
        #pragma unroll
        for (int nt = 0; nt < 4; nt++) {
            int col = n0 + wnBase + nt * 8 + (lane & 3) * 2;
            if (col < PF) {
                *(float2*)&C[(size_t)row * PF + col] =
                    make_float2(acc[mt][nt][0], acc[mt][nt][1]);
                *(float2*)&C[(size_t)(row + 8) * PF + col] =
                    make_float2(acc[mt][nt][2], acc[mt][nt][3]);
            }
        }
    }
}

// ---------------- tiled epilogue: one CTA per (b, 16-row i-chunk) ------------
#define EI 16
#define MAXC (EI + 2 * KW)     // 32 cau rows max
#define EPI_SMEM ((EI + MAXC) * PF * 4)

__global__ void __launch_bounds__(256)
epilogue_kernel(const float* __restrict__ W2, const float* __restrict__ b2,
                float* __restrict__ out) {
    float* sE = (float*)dynraw;            // [EI * PF]
    float* sC = sE + EI * PF;              // [MAXC * PF]

    const int tid  = threadIdx.x;
    const int lane = tid & 31;
    const int wid  = tid >> 5;
    const int i0 = blockIdx.x * EI;
    const int b  = blockIdx.y;

    int j0 = i0 - KW; if (j0 < 0) j0 = 0;
    int j1 = i0 + EI - 1 + KW; if (j1 > L_ - 1) j1 = L_ - 1;
    const int nc = j1 - j0 + 1;

    // W2 into registers (lane-strided float4s)
    float4 wreg[9];
    #pragma unroll
    for (int t = 0; t < 9; t++) {
        int c4 = t * 32 + lane;
        wreg[t] = (c4 < PF / 4) ? ((const float4*)W2)[c4]
                                : make_float4(0.f, 0.f, 0.f, 0.f);
    }
    const float bias = __ldg(b2);

    // stage emo + cau rows
    {
        const float4* src = (const float4*)(g_Aemo + (size_t)(b * L_ + i0) * PF);
        float4* dst = (float4*)sE;
        for (int q = tid; q < EI * PF / 4; q += 256) dst[q] = src[q];
    }
    {
        const float4* src = (const float4*)(g_Acau + (size_t)(b * L_ + j0) * PF);
        float4* dst = (float4*)sC;
        for (int q = tid; q < nc * PF / 4; q += 256) dst[q] = src[q];
    }
    __syncthreads();

    // pairs: q = il*17 + rr, j = i - K + rr
    for (int q = wid; q < EI * NREL; q += 8) {
        int il = q / NREL;
        int rr = q - il * NREL;
        int ii = i0 + il;
        int jj = ii - KW + rr;
        if (jj < 0 || jj > L_ - 1) continue;
        int lo = ii - KW; if (lo < 0) lo = 0;
        int p = g_poff[ii] + (jj - lo);

        const float4* ae = (const float4*)(sE + (size_t)il * PF);
        const float4* ac = (const float4*)(sC + (size_t)(jj - j0) * PF);
        const float4* ap = (const float4*)(g_Apos + (size_t)rr * PF);

        float sum = 0.f;
        #pragma unroll
        for (int t = 0; t < 9; t++) {
            int c4 = t * 32 + lane;
            if (c4 < PF / 4) {
                float4 e = ae[c4];
                float4 c = ac[c4];
                float4 qq = __ldg(&ap[c4]);
                float4 w = wreg[t];
                float v0 = fmaxf(e.x + c.x + qq.x, 0.f);
                float v1 = fmaxf(e.y + c.y + qq.y, 0.f);
                float v2 = fmaxf(e.z + c.z + qq.z, 0.f);
                float v3 = fmaxf(e.w + c.w + qq.w, 0.f);
                sum = fmaf(v0, w.x, sum);
                sum = fmaf(v1, w.y, sum);
                sum = fmaf(v2, w.z, sum);
                sum = fmaf(v3, w.w, sum);
            }
        }
        #pragma unroll
        for (int o = 16; o > 0; o >>= 1)
            sum += __shfl_xor_sync(0xFFFFFFFF, sum, o);
        if (lane == 0) out[b * NPAIR + p] = sum + bias;
    }
}

// ---------------- launch ------------------------------------------------------
extern "C" void kernel_launch(void* const* d_in, const int* in_sizes, int n_in,
                              void* d_out, int out_size) {
    const float* h_emo  = (const float*)d_in[0];
    const float* h_cau  = (const float*)d_in[1];
    const float* pos    = (const float*)d_in[2];
    const float* W1     = (const float*)d_in[3];
    const float* b1     = (const float*)d_in[4];
    const float* W2     = (const float*)d_in[5];
    const float* b2     = (const float*)d_in[6];
    float* out = (float*)d_out;

    const int gemm_smem = NSTAGE * STAGE_ELEMS * (int)sizeof(__nv_bfloat16);
    static bool configured = false;
    if (!configured) {
        cudaFuncSetAttribute(mma_gemm_kernel,
                             cudaFuncAttributeMaxDynamicSharedMemorySize, gemm_smem);
        cudaFuncSetAttribute(epilogue_kernel,
                             cudaFuncAttributeMaxDynamicSharedMemorySize, EPI_SMEM);
        configured = true;
    }

    init_pairs_kernel<<<1, 128>>>(out, out_size);
    init_f_kernel<<<(NREL * PE + 255) / 256, 256>>>(pos);
    init_apos_kernel<<<(NREL * PF + 255) / 256, 256>>>(W1, b1);
    conv_x_kernel<<<(M_ * GCN / 4 + 255) / 256, 256>>>(h_emo, h_cau);
    conv_w_kernel<<<(PF * GCN / 4 + 255) / 256, 256>>>(W1);

    dim3 ggrid(PFP / BN, M_ / BM, 2);   // (9, 16, 2)
    mma_gemm_kernel<<<ggrid, 256, gemm_smem>>>();

    dim3 egrid(L_ / EI, B_);            // (8, 16) = 128 CTAs, one wave
    epilogue_kernel<<<egrid, 256, EPI_SMEM>>>(W2, b2, out);
}